// round 1
// baseline (speedup 1.0000x reference)
#include <cuda_runtime.h>
#include <math.h>

#define B_   64
#define L_   1024
#define ENC_ 2048
#define DEC_ 512
#define ATT_ 512

// Scratch: H[b][a] = (hidden @ W2)[b][a] + b2[a] + b1[a]
__device__ float g_H[B_ * ATT_];

// ---------------------------------------------------------------------------
// Kernel A: H = hidden @ W2 + b2 + b1   (tiny: 64 x 512 x 512)
// ---------------------------------------------------------------------------
__global__ void proj_h_kernel(const float* __restrict__ hidden,
                              const float* __restrict__ W2,
                              const float* __restrict__ b2,
                              const float* __restrict__ b1) {
    __shared__ float hs[DEC_];
    int b = blockIdx.x;
    int a = threadIdx.x;  // 512 threads
    hs[a] = hidden[b * DEC_ + a];
    __syncthreads();
    float acc = 0.f;
#pragma unroll 8
    for (int d = 0; d < DEC_; ++d)
        acc += hs[d] * W2[d * ATT_ + a];
    g_H[b * ATT_ + a] = acc + b2[a] + b1[a];
}

// ---------------------------------------------------------------------------
// Kernel B: fused  score[m] = sum_a tanh( (F @ W1)[m][a] + H[b][a] ) * V[a] + bv
// Tiled SGEMM 128x128x8, 8x8 microtile, 256 threads. proj_f never hits GMEM.
// ---------------------------------------------------------------------------
__global__ __launch_bounds__(256, 2) void score_kernel(
    const float* __restrict__ F,   // [B*L, ENC]
    const float* __restrict__ W1,  // [ENC, ATT]
    const float* __restrict__ V,   // [ATT]
    const float* __restrict__ bv,  // [1]
    float* __restrict__ score)     // [B*L]
{
    constexpr int BM = 128, BN = 128, BK = 8;
    __shared__ float As[BK][BM];   // transposed feature tile
    __shared__ float Bs[BK][BN];   // W1 tile

    const int tid = threadIdx.x;
    const int tx  = tid & 15;      // 0..15  -> col group (8 cols)
    const int ty  = tid >> 4;      // 0..15  -> row group (8 rows)
    const int m0  = blockIdx.x * BM;
    const int b   = m0 / L_;       // 1024 % 128 == 0 -> one batch per CTA

    // global->smem load assignments
    const int arow = tid >> 1;            // 0..127
    const int akq  = (tid & 1) * 4;       // 0 or 4
    const int bkk  = tid >> 5;            // 0..7
    const int bc4  = (tid & 31) * 4;      // 0..124

    float rowsum[8];
#pragma unroll
    for (int i = 0; i < 8; ++i) rowsum[i] = 0.f;

#pragma unroll 1
    for (int chunk = 0; chunk < ATT_ / BN; ++chunk) {
        const int n0 = chunk * BN;
        float acc[8][8];
#pragma unroll
        for (int i = 0; i < 8; ++i)
#pragma unroll
            for (int j = 0; j < 8; ++j) acc[i][j] = 0.f;

        for (int k0 = 0; k0 < ENC_; k0 += BK) {
            __syncthreads();
            // A tile: 128 rows x 8 k (transposed into As[k][m])
            float4 av = *reinterpret_cast<const float4*>(
                &F[(size_t)(m0 + arow) * ENC_ + k0 + akq]);
            As[akq + 0][arow] = av.x;
            As[akq + 1][arow] = av.y;
            As[akq + 2][arow] = av.z;
            As[akq + 3][arow] = av.w;
            // B tile: 8 k x 128 n
            *reinterpret_cast<float4*>(&Bs[bkk][bc4]) =
                *reinterpret_cast<const float4*>(
                    &W1[(size_t)(k0 + bkk) * ATT_ + n0 + bc4]);
            __syncthreads();

#pragma unroll
            for (int kk = 0; kk < BK; ++kk) {
                float4 a0 = *reinterpret_cast<const float4*>(&As[kk][ty * 8]);
                float4 a1 = *reinterpret_cast<const float4*>(&As[kk][ty * 8 + 4]);
                float4 c0 = *reinterpret_cast<const float4*>(&Bs[kk][tx * 8]);
                float4 c1 = *reinterpret_cast<const float4*>(&Bs[kk][tx * 8 + 4]);
                float a[8] = {a0.x, a0.y, a0.z, a0.w, a1.x, a1.y, a1.z, a1.w};
                float c[8] = {c0.x, c0.y, c0.z, c0.w, c1.x, c1.y, c1.z, c1.w};
#pragma unroll
                for (int i = 0; i < 8; ++i)
#pragma unroll
                    for (int j = 0; j < 8; ++j)
                        acc[i][j] += a[i] * c[j];
            }
        }

        // fused epilogue: tanh + V-weighted reduction over ATT columns
#pragma unroll
        for (int j = 0; j < 8; ++j) {
            const int col = n0 + tx * 8 + j;
            const float h = g_H[b * ATT_ + col];
            const float v = V[col];
#pragma unroll
            for (int i = 0; i < 8; ++i)
                rowsum[i] += tanhf(acc[i][j] + h) * v;
        }
    }

    // reduce across the 16 threads (same ty, lanes (ty&1)*16 + tx) sharing rows
#pragma unroll
    for (int i = 0; i < 8; ++i) {
#pragma unroll
        for (int off = 8; off > 0; off >>= 1)
            rowsum[i] += __shfl_xor_sync(0xffffffffu, rowsum[i], off);
    }
    if (tx == 0) {
        const float bvv = bv[0];
#pragma unroll
        for (int i = 0; i < 8; ++i)
            score[m0 + ty * 8 + i] = rowsum[i] + bvv;
    }
}

// ---------------------------------------------------------------------------
// Kernel C: in-place softmax over L per batch (scores -> weights)
// ---------------------------------------------------------------------------
__global__ void softmax_kernel(float* __restrict__ w) {
    __shared__ float redm[32];
    __shared__ float reds[32];
    const int b = blockIdx.x;
    const int t = threadIdx.x;  // 1024 threads
    float s = w[b * L_ + t];

    // block max
    float m = s;
#pragma unroll
    for (int off = 16; off > 0; off >>= 1)
        m = fmaxf(m, __shfl_xor_sync(0xffffffffu, m, off));
    if ((t & 31) == 0) redm[t >> 5] = m;
    __syncthreads();
    if (t < 32) {
        float v = redm[t];
#pragma unroll
        for (int off = 16; off > 0; off >>= 1)
            v = fmaxf(v, __shfl_xor_sync(0xffffffffu, v, off));
        redm[t] = v;
    }
    __syncthreads();
    m = redm[0];

    const float e = expf(s - m);
    float sum = e;
#pragma unroll
    for (int off = 16; off > 0; off >>= 1)
        sum += __shfl_xor_sync(0xffffffffu, sum, off);
    if ((t & 31) == 0) reds[t >> 5] = sum;
    __syncthreads();
    if (t < 32) {
        float v = reds[t];
#pragma unroll
        for (int off = 16; off > 0; off >>= 1)
            v += __shfl_xor_sync(0xffffffffu, v, off);
        reds[t] = v;
    }
    __syncthreads();
    w[b * L_ + t] = e / reds[0];
}

// ---------------------------------------------------------------------------
// Kernel D: context[b][e] = sum_l w[b][l] * F[b][l][e]   (memory-bound GEMV)
// ---------------------------------------------------------------------------
__global__ void context_kernel(const float* __restrict__ F,
                               const float* __restrict__ w,
                               float* __restrict__ ctx) {
    __shared__ float ws[L_];
    const int b = blockIdx.y;
    const int t = threadIdx.x;  // 128 threads
    for (int l = t; l < L_; l += 128) ws[l] = w[b * L_ + l];
    __syncthreads();

    const int e0 = blockIdx.x * 512 + t * 4;
    const float* fb = F + (size_t)b * L_ * ENC_ + e0;
    float4 acc = make_float4(0.f, 0.f, 0.f, 0.f);
#pragma unroll 4
    for (int l = 0; l < L_; ++l) {
        float4 f = *reinterpret_cast<const float4*>(fb + (size_t)l * ENC_);
        const float wl = ws[l];
        acc.x += wl * f.x;
        acc.y += wl * f.y;
        acc.z += wl * f.z;
        acc.w += wl * f.w;
    }
    *reinterpret_cast<float4*>(&ctx[b * ENC_ + e0]) = acc;
}

// ---------------------------------------------------------------------------
// Launch. Inputs (metadata order): features, hidden_state, W1, b1, W2, b2, V, bv
// Output: [context (64*2048) | attention_weights (64*1024)] fp32
// ---------------------------------------------------------------------------
extern "C" void kernel_launch(void* const* d_in, const int* in_sizes, int n_in,
                              void* d_out, int out_size) {
    const float* F   = (const float*)d_in[0];
    const float* hid = (const float*)d_in[1];
    const float* W1  = (const float*)d_in[2];
    const float* b1  = (const float*)d_in[3];
    const float* W2  = (const float*)d_in[4];
    const float* b2  = (const float*)d_in[5];
    const float* V   = (const float*)d_in[6];
    const float* bv  = (const float*)d_in[7];

    float* out = (float*)d_out;
    float* ctx = out;               // [64, 2048]
    float* wts = out + B_ * ENC_;   // [64, 1024] (scores written here, softmaxed in place)

    proj_h_kernel<<<B_, ATT_>>>(hid, W2, b2, b1);
    score_kernel<<<(B_ * L_) / 128, 256>>>(F, W1, V, bv, wts);
    softmax_kernel<<<B_, L_>>>(wts);
    context_kernel<<<dim3(ENC_ / 512, B_), 128>>>(F, wts, ctx);
}

// round 3
// speedup vs baseline: 2.8189x; 2.8189x over previous
#include <cuda_runtime.h>
#include <cuda_bf16.h>
#include <math.h>
#include <stdint.h>

#define B_   64
#define L_   1024
#define ENC_ 2048
#define DEC_ 512
#define ATT_ 512
#define BL_  (B_ * L_)

// ---------------------------------------------------------------------------
// Device scratch
// ---------------------------------------------------------------------------
__device__ float g_H[B_ * ATT_];                             // proj_h + b2 + b1
// W1 split into bf16 hi/lo, layout [kchunk c][n 512][k 32] (K-major per chunk)
__device__ __align__(128) __nv_bfloat16 g_Bhi[ENC_ * ATT_];
__device__ __align__(128) __nv_bfloat16 g_Blo[ENC_ * ATT_];
__device__ float g_scorep[4 * BL_];                          // per-N-chunk score partials
__device__ float g_ctxp[4 * B_ * ENC_];                      // context partials

// ---------------------------------------------------------------------------
// Helpers
// ---------------------------------------------------------------------------
__device__ __forceinline__ uint32_t smem_u32(const void* p) {
    uint32_t a;
    asm("{ .reg .u64 t; cvta.to.shared.u64 t, %1; cvt.u32.u64 %0, t; }" : "=r"(a) : "l"(p));
    return a;
}
__device__ __forceinline__ void cp16(uint32_t dst, const void* src) {
    asm volatile("cp.async.cg.shared.global [%0], [%1], 16;" :: "r"(dst), "l"(src));
}
__device__ __forceinline__ void cp_commit() {
    asm volatile("cp.async.commit_group;" ::: "memory");
}
__device__ __forceinline__ void cp_wait0() {
    asm volatile("cp.async.wait_group 0;" ::: "memory");
}
__device__ __forceinline__ void ldsm_x4(uint32_t* r, uint32_t addr) {
    asm volatile("ldmatrix.sync.aligned.m8n8.x4.shared.b16 {%0,%1,%2,%3}, [%4];"
                 : "=r"(r[0]), "=r"(r[1]), "=r"(r[2]), "=r"(r[3]) : "r"(addr));
}
__device__ __forceinline__ void ldsm_x2(uint32_t* r, uint32_t addr) {
    asm volatile("ldmatrix.sync.aligned.m8n8.x2.shared.b16 {%0,%1}, [%2];"
                 : "=r"(r[0]), "=r"(r[1]) : "r"(addr));
}
__device__ __forceinline__ void mma_bf16(float* d, const uint32_t* a, const uint32_t* b) {
    asm volatile(
        "mma.sync.aligned.m16n8k16.row.col.f32.bf16.bf16.f32 "
        "{%0,%1,%2,%3}, {%4,%5,%6,%7}, {%8,%9}, {%0,%1,%2,%3};"
        : "+f"(d[0]), "+f"(d[1]), "+f"(d[2]), "+f"(d[3])
        : "r"(a[0]), "r"(a[1]), "r"(a[2]), "r"(a[3]), "r"(b[0]), "r"(b[1]));
}
__device__ __forceinline__ float fast_tanh(float x) {
    float e = __expf(2.f * x);
    return __fdividef(e - 1.f, e + 1.f);
}

// ---------------------------------------------------------------------------
// Kernel A: H = hidden @ W2 + b2 + b1
// ---------------------------------------------------------------------------
__global__ void proj_h_kernel(const float* __restrict__ hidden,
                              const float* __restrict__ W2,
                              const float* __restrict__ b2,
                              const float* __restrict__ b1) {
    __shared__ float hs[DEC_];
    int b = blockIdx.x, a = threadIdx.x;
    hs[a] = hidden[b * DEC_ + a];
    __syncthreads();
    float acc = 0.f;
#pragma unroll 8
    for (int d = 0; d < DEC_; ++d) acc += hs[d] * W2[d * ATT_ + a];
    g_H[b * ATT_ + a] = acc + b2[a] + b1[a];
}

// ---------------------------------------------------------------------------
// Kernel B: split W1 [ENC, ATT] fp32 -> bf16 hi/lo, layout [c][n][k32]
// ---------------------------------------------------------------------------
__global__ void prep_B_kernel(const float* __restrict__ W1) {
    int idx = blockIdx.x * 256 + threadIdx.x;   // idx = k*512 + n
    if (idx >= ENC_ * ATT_) return;
    int k = idx >> 9, n = idx & 511;
    float x = W1[idx];
    __nv_bfloat16 h = __float2bfloat16(x);
    __nv_bfloat16 l = __float2bfloat16(x - __bfloat162float(h));
    int c = k >> 5, kk = k & 31;
    size_t o = ((size_t)(c * 512 + n) << 5) + kk;
    g_Bhi[o] = h;
    g_Blo[o] = l;
}

// ---------------------------------------------------------------------------
// Kernel C: fused bf16x3 mma.sync GEMM + tanh + V-reduction -> score partials
// Grid: (512 m-tiles, 4 n-chunks). CTA: 128x128 tile, K=2048, KC=32 staged x2.
// ---------------------------------------------------------------------------
static constexpr int KC      = 32;
static constexpr int PITCH   = 80;          // bytes per row (32 bf16 + 8 pad)
static constexpr int HALF_SZ = 128 * PITCH; // 10240
static constexpr int STAGE   = 4 * HALF_SZ; // Ahi,Alo,Bhi,Blo = 40960
static constexpr int OFF_AHI = 0;
static constexpr int OFF_ALO = HALF_SZ;
static constexpr int OFF_BHI = 2 * HALF_SZ;
static constexpr int OFF_BLO = 3 * HALF_SZ;
static constexpr int OFF_PART = 2 * STAGE;           // 81920, 2*128 floats
static constexpr int OFF_H    = OFF_PART + 1024;     // 128 floats
static constexpr int OFF_V    = OFF_H + 512;         // 128 floats
static constexpr int SMEM_TOTAL = OFF_V + 512;       // 84480

__global__ __launch_bounds__(256, 1) void score_mma_kernel(
    const float* __restrict__ F,
    const float* __restrict__ V)
{
    extern __shared__ char smem[];
    const uint32_t sb = smem_u32(smem);
    const int tid  = threadIdx.x;
    const int lane = tid & 31;
    const int wid  = tid >> 5;
    const int wm   = wid & 3;        // warp m: 4 x 32 rows
    const int wn   = wid >> 2;       // warp n: 2 x 64 cols
    const int m0   = blockIdx.x * 128;
    const int nc   = blockIdx.y;     // n chunk (128 cols)
    const int b    = blockIdx.x >> 3;

    float* partS = (float*)(smem + OFF_PART);
    float* Hs    = (float*)(smem + OFF_H);
    float* Vs    = (float*)(smem + OFF_V);
    if (tid < 128) {
        Hs[tid] = g_H[b * ATT_ + nc * 128 + tid];
        Vs[tid] = V[nc * 128 + tid];
    }

    // per-thread load assignments
    const int arow = tid >> 1;                // A: 128 rows x 2 halves? (see below)
    (void)arow;
    // A: 1024 float4 per chunk -> 4 per thread: v = tid + j*256, row=v>>3, q=v&7
    // B: 512 16B-chunks per half -> 2 per thread: j = tid*2 + e, row=j>>2, q=j&3

    const __nv_bfloat16* gBh = g_Bhi;
    const __nv_bfloat16* gBl = g_Blo;

    float d[2][8][4];
#pragma unroll
    for (int mt = 0; mt < 2; ++mt)
#pragma unroll
        for (int nt = 0; nt < 8; ++nt)
#pragma unroll
            for (int e = 0; e < 4; ++e) d[mt][nt][e] = 0.f;

    float4 fr[4];

    // ---- prologue: chunk 0 ----
    {
        const float* Fp = F + (size_t)m0 * ENC_;
#pragma unroll
        for (int j = 0; j < 4; ++j) {
            int v = tid + j * 256, row = v >> 3, q = v & 7;
            fr[j] = *(const float4*)(Fp + (size_t)row * ENC_ + q * 4);
        }
        // B chunk 0 -> stage 0
        const __nv_bfloat16* srcH = gBh + ((size_t)(0 * 512 + nc * 128) << 5);
        const __nv_bfloat16* srcL = gBl + ((size_t)(0 * 512 + nc * 128) << 5);
#pragma unroll
        for (int e = 0; e < 2; ++e) {
            int j = tid * 2 + e, row = j >> 2, q = j & 3;
            cp16(sb + OFF_BHI + row * PITCH + q * 16, srcH + (row << 5) + q * 8);
            cp16(sb + OFF_BLO + row * PITCH + q * 16, srcL + (row << 5) + q * 8);
        }
        cp_commit();
        // A chunk 0 -> stage 0
#pragma unroll
        for (int j = 0; j < 4; ++j) {
            int v = tid + j * 256, row = v >> 3, q = v & 7;
            float4 f = fr[j];
            __nv_bfloat162 h01 = __floats2bfloat162_rn(f.x, f.y);
            __nv_bfloat162 h23 = __floats2bfloat162_rn(f.z, f.w);
            __nv_bfloat162 l01 = __floats2bfloat162_rn(f.x - __low2float(h01),
                                                       f.y - __high2float(h01));
            __nv_bfloat162 l23 = __floats2bfloat162_rn(f.z - __low2float(h23),
                                                       f.w - __high2float(h23));
            uint32_t o = row * PITCH + q * 8;
            *(uint2*)(smem + OFF_AHI + o) = make_uint2(*(uint32_t*)&h01, *(uint32_t*)&h23);
            *(uint2*)(smem + OFF_ALO + o) = make_uint2(*(uint32_t*)&l01, *(uint32_t*)&l23);
        }
    }

    const uint32_t a_lrow = (uint32_t)(wm * 32 + (lane & 15));
    const uint32_t a_loff = (uint32_t)(((lane >> 4) & 1) * 16);
    const uint32_t b_lrow = (uint32_t)(wn * 64 + (lane & 7));
    const uint32_t b_loff = (uint32_t)(((lane >> 3) & 1) * 16);

#pragma unroll 1
    for (int i = 0; i < ENC_ / KC; ++i) {
        const int s = i & 1;
        const uint32_t stg = sb + s * STAGE;
        const uint32_t nstg = sb + (s ^ 1) * STAGE;

        // prefetch A(i+1) into regs (overlaps the cp.async wait + compute)
        if (i + 1 < ENC_ / KC) {
            const float* Fp = F + (size_t)m0 * ENC_ + (i + 1) * KC;
#pragma unroll
            for (int j = 0; j < 4; ++j) {
                int v = tid + j * 256, row = v >> 3, q = v & 7;
                fr[j] = *(const float4*)(Fp + (size_t)row * ENC_ + q * 4);
            }
        }

        cp_wait0();
        __syncthreads();   // stage s fully populated; prev compute done with s^1

        if (i + 1 < ENC_ / KC) {
            const __nv_bfloat16* srcH = gBh + ((size_t)((i + 1) * 512 + nc * 128) << 5);
            const __nv_bfloat16* srcL = gBl + ((size_t)((i + 1) * 512 + nc * 128) << 5);
#pragma unroll
            for (int e = 0; e < 2; ++e) {
                int j = tid * 2 + e, row = j >> 2, q = j & 3;
                cp16(nstg + OFF_BHI + row * PITCH + q * 16, srcH + (row << 5) + q * 8);
                cp16(nstg + OFF_BLO + row * PITCH + q * 16, srcL + (row << 5) + q * 8);
            }
            cp_commit();
#pragma unroll
            for (int j = 0; j < 4; ++j) {
                int v = tid + j * 256, row = v >> 3, q = v & 7;
                float4 f = fr[j];
                __nv_bfloat162 h01 = __floats2bfloat162_rn(f.x, f.y);
                __nv_bfloat162 h23 = __floats2bfloat162_rn(f.z, f.w);
                __nv_bfloat162 l01 = __floats2bfloat162_rn(f.x - __low2float(h01),
                                                           f.y - __high2float(h01));
                __nv_bfloat162 l23 = __floats2bfloat162_rn(f.z - __low2float(h23),
                                                           f.w - __high2float(h23));
                uint32_t o = row * PITCH + q * 8;
                *(uint2*)((char*)smem + (s ^ 1) * STAGE + OFF_AHI + o) =
                    make_uint2(*(uint32_t*)&h01, *(uint32_t*)&h23);
                *(uint2*)((char*)smem + (s ^ 1) * STAGE + OFF_ALO + o) =
                    make_uint2(*(uint32_t*)&l01, *(uint32_t*)&l23);
            }
        }

        // ---- compute chunk i on stage s ----
#pragma unroll
        for (int kk = 0; kk < 2; ++kk) {
            const uint32_t ko = (uint32_t)(kk * 32);
            uint32_t ah0[4], ah1[4], al0[4], al1[4];
            ldsm_x4(ah0, stg + OFF_AHI + a_lrow * PITCH + a_loff + ko);
            ldsm_x4(ah1, stg + OFF_AHI + (a_lrow + 16) * PITCH + a_loff + ko);
            ldsm_x4(al0, stg + OFF_ALO + a_lrow * PITCH + a_loff + ko);
            ldsm_x4(al1, stg + OFF_ALO + (a_lrow + 16) * PITCH + a_loff + ko);
            uint32_t bh[8][2], bl[8][2];
#pragma unroll
            for (int nt = 0; nt < 8; ++nt) {
                ldsm_x2(bh[nt], stg + OFF_BHI + (b_lrow + nt * 8) * PITCH + b_loff + ko);
                ldsm_x2(bl[nt], stg + OFF_BLO + (b_lrow + nt * 8) * PITCH + b_loff + ko);
            }
#pragma unroll
            for (int nt = 0; nt < 8; ++nt) {
                mma_bf16(d[0][nt], ah0, bh[nt]);
                mma_bf16(d[1][nt], ah1, bh[nt]);
                mma_bf16(d[0][nt], ah0, bl[nt]);
                mma_bf16(d[1][nt], ah1, bl[nt]);
                mma_bf16(d[0][nt], al0, bh[nt]);
                mma_bf16(d[1][nt], al1, bh[nt]);
            }
        }
    }

    // ---- epilogue: tanh + V-weighted row reduction over this 128-col chunk ----
#pragma unroll
    for (int mt = 0; mt < 2; ++mt) {
        float s0 = 0.f, s1 = 0.f;
#pragma unroll
        for (int nt = 0; nt < 8; ++nt) {
            int c0 = wn * 64 + nt * 8 + (lane & 3) * 2;
            float h0 = Hs[c0], v0 = Vs[c0];
            float h1 = Hs[c0 + 1], v1 = Vs[c0 + 1];
            s0 += fast_tanh(d[mt][nt][0] + h0) * v0 + fast_tanh(d[mt][nt][1] + h1) * v1;
            s1 += fast_tanh(d[mt][nt][2] + h0) * v0 + fast_tanh(d[mt][nt][3] + h1) * v1;
        }
#pragma unroll
        for (int o = 1; o <= 2; o <<= 1) {
            s0 += __shfl_xor_sync(~0u, s0, o);
            s1 += __shfl_xor_sync(~0u, s1, o);
        }
        if ((lane & 3) == 0) {
            int r = wm * 32 + mt * 16 + (lane >> 2);
            partS[wn * 128 + r]     = s0;
            partS[wn * 128 + r + 8] = s1;
        }
    }
    __syncthreads();
    if (tid < 128)
        g_scorep[nc * BL_ + m0 + tid] = partS[tid] + partS[128 + tid];
}

// ---------------------------------------------------------------------------
// Kernel D: combine partials + softmax over L per batch
// ---------------------------------------------------------------------------
__global__ void softmax_kernel(const float* __restrict__ bv, float* __restrict__ w) {
    __shared__ float redm[32];
    __shared__ float reds[32];
    const int b = blockIdx.x, t = threadIdx.x;
    const int idx = b * L_ + t;
    float s = g_scorep[idx] + g_scorep[BL_ + idx] + g_scorep[2 * BL_ + idx] +
              g_scorep[3 * BL_ + idx] + bv[0];
    float m = s;
#pragma unroll
    for (int o = 16; o > 0; o >>= 1) m = fmaxf(m, __shfl_xor_sync(~0u, m, o));
    if ((t & 31) == 0) redm[t >> 5] = m;
    __syncthreads();
    if (t < 32) {
        float v = redm[t];
#pragma unroll
        for (int o = 16; o > 0; o >>= 1) v = fmaxf(v, __shfl_xor_sync(~0u, v, o));
        redm[t] = v;
    }
    __syncthreads();
    m = redm[0];
    const float e = expf(s - m);
    float sum = e;
#pragma unroll
    for (int o = 16; o > 0; o >>= 1) sum += __shfl_xor_sync(~0u, sum, o);
    if ((t & 31) == 0) reds[t >> 5] = sum;
    __syncthreads();
    if (t < 32) {
        float v = reds[t];
#pragma unroll
        for (int o = 16; o > 0; o >>= 1) v += __shfl_xor_sync(~0u, v, o);
        reds[t] = v;
    }
    __syncthreads();
    w[idx] = e / reds[0];
}

// ---------------------------------------------------------------------------
// Kernel E/F: context = sum_l w*F  (L split in 4 partials, then reduced)
// ---------------------------------------------------------------------------
__global__ void context_part_kernel(const float* __restrict__ F,
                                    const float* __restrict__ w) {
    __shared__ float ws[256];
    const int b = blockIdx.y, z = blockIdx.z, t = threadIdx.x;
    const int l0 = z * 256;
    for (int l = t; l < 256; l += 128) ws[l] = w[b * L_ + l0 + l];
    __syncthreads();
    const int e0 = blockIdx.x * 512 + t * 4;
    const float* fb = F + (size_t)b * L_ * ENC_ + (size_t)l0 * ENC_ + e0;
    float4 acc = make_float4(0.f, 0.f, 0.f, 0.f);
#pragma unroll 4
    for (int l = 0; l < 256; ++l) {
        float4 f = *(const float4*)(fb + (size_t)l * ENC_);
        const float wl = ws[l];
        acc.x += wl * f.x; acc.y += wl * f.y; acc.z += wl * f.z; acc.w += wl * f.w;
    }
    *(float4*)&g_ctxp[(size_t)(z * B_ + b) * ENC_ + e0] = acc;
}

__global__ void context_reduce_kernel(float* __restrict__ ctx) {
    const int i = (blockIdx.x * 256 + threadIdx.x) * 4;
    float4 a = *(const float4*)&g_ctxp[i];
    float4 c = *(const float4*)&g_ctxp[B_ * ENC_ + i];
    float4 d = *(const float4*)&g_ctxp[2 * B_ * ENC_ + i];
    float4 e = *(const float4*)&g_ctxp[3 * B_ * ENC_ + i];
    *(float4*)&ctx[i] = make_float4(a.x + c.x + d.x + e.x, a.y + c.y + d.y + e.y,
                                    a.z + c.z + d.z + e.z, a.w + c.w + d.w + e.w);
}

// ---------------------------------------------------------------------------
// Launch
// ---------------------------------------------------------------------------
extern "C" void kernel_launch(void* const* d_in, const int* in_sizes, int n_in,
                              void* d_out, int out_size) {
    const float* F   = (const float*)d_in[0];
    const float* hid = (const float*)d_in[1];
    const float* W1  = (const float*)d_in[2];
    const float* b1  = (const float*)d_in[3];
    const float* W2  = (const float*)d_in[4];
    const float* b2  = (const float*)d_in[5];
    const float* V   = (const float*)d_in[6];
    const float* bv  = (const float*)d_in[7];

    float* out = (float*)d_out;
    float* ctx = out;
    float* wts = out + B_ * ENC_;

    static bool attr_set = false;
    if (!attr_set) {
        cudaFuncSetAttribute(score_mma_kernel,
                             cudaFuncAttributeMaxDynamicSharedMemorySize, SMEM_TOTAL);
        attr_set = true;
    }

    proj_h_kernel<<<B_, ATT_>>>(hid, W2, b2, b1);
    prep_B_kernel<<<(ENC_ * ATT_) / 256, 256>>>(W1);
    score_mma_kernel<<<dim3(BL_ / 128, 4), 256, SMEM_TOTAL>>>(F, V);
    softmax_kernel<<<B_, L_>>>(bv, wts);
    context_part_kernel<<<dim3(ENC_ / 512, B_, 4), 128>>>(F, wts);
    context_reduce_kernel<<<(B_ * ENC_) / 1024, 256>>>(ctx);
}